// round 1
// baseline (speedup 1.0000x reference)
#include <cuda_runtime.h>
#include <math.h>

#define BDIM   256
#define DD     64
#define OO     32
#define KMIX   15
#define HIDN   60
#define PITCH  68   // row pitch (floats) for 64-wide tiles: float4-aligned, conflict-free row reads
#define SPITCH 36   // row pitch for 32-wide tiles
#define LOG2PI 1.8378770664093453f

// smem layout (floats)
#define OFF_P    0
#define OFF_FT   (OFF_P   + DD*PITCH)
#define OFF_T    (OFF_FT  + DD*PITCH)
#define OFF_HP   (OFF_T   + DD*PITCH)
#define OFF_HW   (OFF_HP  + OO*PITCH)
#define OFF_S    (OFF_HW  + OO*PITCH)
#define OFF_LI   (OFF_S   + OO*SPITCH)
#define OFF_SI   (OFF_LI  + OO*SPITCH)
#define OFF_KG   (OFF_SI  + OO*SPITCH)
#define OFF_M    (OFF_KG  + DD*SPITCH)
#define OFF_PM   (OFF_M   + DD)
#define OFF_INN  (OFF_PM  + DD)
#define OFF_H    (OFF_INN + OO)
#define OFF_W    (OFF_H   + DD)
#define OFF_RED  (OFF_W   + 16)
#define SMEM_FLOATS (OFF_RED + 4)

__device__ __forceinline__ float4 ld4(const float* p){ return *reinterpret_cast<const float4*>(p); }
__device__ __forceinline__ void   st4(float* p, float4 v){ *reinterpret_cast<float4*>(p) = v; }
__device__ __forceinline__ float4 fma4(float a, float4 b, float4 c){
    c.x = fmaf(a,b.x,c.x); c.y = fmaf(a,b.y,c.y);
    c.z = fmaf(a,b.z,c.z); c.w = fmaf(a,b.w,c.w);
    return c;
}
__device__ __forceinline__ float dot4acc(float4 a, float4 b, float c){
    c = fmaf(a.x,b.x,c); c = fmaf(a.y,b.y,c);
    c = fmaf(a.z,b.z,c); c = fmaf(a.w,b.w,c);
    return c;
}

__global__ __launch_bounds__(BDIM, 2)
void rkn_kernel(const float* __restrict__ g_mean,
                const float* __restrict__ g_cov,
                const float* __restrict__ g_obs,
                const float* __restrict__ g_w1,
                const float* __restrict__ g_b1,
                const float* __restrict__ g_w2,
                const float* __restrict__ g_b2,
                const float* __restrict__ g_basis,
                const float* __restrict__ g_pnf,
                const float* __restrict__ g_pnd,
                const float* __restrict__ g_onf,
                const float* __restrict__ g_ond,
                const float* __restrict__ g_Hw,
                const float* __restrict__ g_Hb,
                float* __restrict__ o_mean,
                float* __restrict__ o_cov,
                float* __restrict__ o_ll)
{
    extern __shared__ float smem[];
    float* sP   = smem + OFF_P;    // P, later pred_cov (in place)
    float* sFt  = smem + OFF_FT;   // F transposed: sFt[k*PITCH+i] = F[i][k]
    float* sT   = smem + OFF_T;    // T = F @ P
    float* sHP  = smem + OFF_HP;   // HP = Hw @ pred_cov  [32][64]
    float* sHw  = smem + OFF_HW;   // Hw [32][64]
    float* sS   = smem + OFF_S;    // S, then L in place  [32][32]
    float* sLi  = smem + OFF_LI;   // L^{-1}
    float* sSi  = smem + OFF_SI;   // S^{-1}
    float* sKg  = smem + OFF_KG;   // Kalman gain [64][32]
    float* sm_  = smem + OFF_M;    // state_mean
    float* spm  = smem + OFF_PM;   // pred_mean
    float* sinn = smem + OFF_INN;  // innovation
    float* sh   = smem + OFF_H;    // hidden
    float* sw   = smem + OFF_W;    // mixture weights
    float* sred = smem + OFF_RED;  // log_det

    const int b   = blockIdx.x;
    const int tid = threadIdx.x;
    const int tx  = tid & 15;
    const int ty  = tid >> 4;

    // ---------------- loads ----------------
    if (tid < DD) sm_[tid] = g_mean[b*DD + tid];
    {   // Hw: 2048 floats, 8 per thread
        int base = tid * 8;
        int r = base >> 6, c = base & 63;
        st4(sHw + r*PITCH + c,     ld4(g_Hw + base));
        st4(sHw + r*PITCH + c + 4, ld4(g_Hw + base + 4));
    }
    {   // P: 4096 floats, 16 per thread
        const float* Pg = g_cov + (size_t)b*DD*DD;
        int base = tid*16;
        #pragma unroll
        for (int q=0;q<4;q++){
            int g = base + q*4;
            st4(sP + (g>>6)*PITCH + (g&63), ld4(Pg + g));
        }
    }
    __syncthreads();

    // ---------------- MLP ----------------
    if (tid < HIDN) {
        float acc = g_b1[tid];
        const float* w1r = g_w1 + tid*DD;
        #pragma unroll 16
        for (int d=0; d<DD; d++) acc = fmaf(w1r[d], sm_[d], acc);
        sh[tid] = acc > 0.f ? acc : expm1f(acc);   // elu
    }
    __syncthreads();
    if (tid < KMIX) {
        float acc = g_b2[tid];
        const float* w2r = g_w2 + tid*HIDN;
        #pragma unroll 15
        for (int j=0;j<HIDN;j++) acc = fmaf(w2r[j], sh[j], acc);
        sw[tid] = acc;
    }
    __syncthreads();
    if (tid == 0) {   // softmax over 15
        float mx = sw[0];
        #pragma unroll
        for (int k=1;k<KMIX;k++) mx = fmaxf(mx, sw[k]);
        float s = 0.f;
        #pragma unroll
        for (int k=0;k<KMIX;k++){ float e = expf(sw[k]-mx); sw[k]=e; s+=e; }
        float inv = 1.f/s;
        #pragma unroll
        for (int k=0;k<KMIX;k++) sw[k] *= inv;
    }
    __syncthreads();

    // ---------------- F = sum_k w_k basis_k (stored transposed) ----------------
    {
        float wl[KMIX];
        #pragma unroll
        for (int k=0;k<KMIX;k++) wl[k] = sw[k];
        int base = tid*16;
        int r = base >> 6;
        #pragma unroll
        for (int q=0;q<4;q++){
            int g = base + q*4;
            float4 acc = make_float4(0.f,0.f,0.f,0.f);
            #pragma unroll
            for (int k=0;k<KMIX;k++){
                float4 v = ld4(g_basis + k*4096 + g);
                acc = fma4(wl[k], v, acc);
            }
            int c = g & 63;
            sFt[(c+0)*PITCH + r] = acc.x;
            sFt[(c+1)*PITCH + r] = acc.y;
            sFt[(c+2)*PITCH + r] = acc.z;
            sFt[(c+3)*PITCH + r] = acc.w;
        }
    }
    __syncthreads();

    // pred_mean = F @ m
    if (tid < DD) {
        float acc = 0.f;
        #pragma unroll 16
        for (int k=0;k<DD;k++) acc = fmaf(sFt[k*PITCH + tid], sm_[k], acc);
        spm[tid] = acc;
    }

    // ---------------- GEMM1: T = F @ P ----------------
    {
        const int r0 = ty*4, c0 = tx*4;
        float4 acc0=make_float4(0,0,0,0), acc1=acc0, acc2=acc0, acc3=acc0;
        for (int k=0;k<DD;k+=4){
            float4 a0 = ld4(sFt + (k+0)*PITCH + r0);
            float4 a1 = ld4(sFt + (k+1)*PITCH + r0);
            float4 a2 = ld4(sFt + (k+2)*PITCH + r0);
            float4 a3 = ld4(sFt + (k+3)*PITCH + r0);
            float4 p0 = ld4(sP + (k+0)*PITCH + c0);
            acc0=fma4(a0.x,p0,acc0); acc1=fma4(a0.y,p0,acc1); acc2=fma4(a0.z,p0,acc2); acc3=fma4(a0.w,p0,acc3);
            float4 p1 = ld4(sP + (k+1)*PITCH + c0);
            acc0=fma4(a1.x,p1,acc0); acc1=fma4(a1.y,p1,acc1); acc2=fma4(a1.z,p1,acc2); acc3=fma4(a1.w,p1,acc3);
            float4 p2 = ld4(sP + (k+2)*PITCH + c0);
            acc0=fma4(a2.x,p2,acc0); acc1=fma4(a2.y,p2,acc1); acc2=fma4(a2.z,p2,acc2); acc3=fma4(a2.w,p2,acc3);
            float4 p3 = ld4(sP + (k+3)*PITCH + c0);
            acc0=fma4(a3.x,p3,acc0); acc1=fma4(a3.y,p3,acc1); acc2=fma4(a3.z,p3,acc2); acc3=fma4(a3.w,p3,acc3);
        }
        st4(sT + (r0+0)*PITCH + c0, acc0);
        st4(sT + (r0+1)*PITCH + c0, acc1);
        st4(sT + (r0+2)*PITCH + c0, acc2);
        st4(sT + (r0+3)*PITCH + c0, acc3);
    }
    __syncthreads();

    // innovation (overlapped with GEMM2 by other threads)
    if (tid < OO) {
        float acc = g_Hb[tid];
        #pragma unroll 8
        for (int k=0;k<DD;k++) acc = fmaf(sHw[tid*PITCH+k], spm[k], acc);
        sinn[tid] = g_obs[b*OO + tid] - acc;
    }

    // ---------------- GEMM2: pred_cov = T @ F^T + Q (into sP) ----------------
    {
        const int r0 = ty*4, c0 = tx*4;
        float4 acc0=make_float4(0,0,0,0), acc1=acc0, acc2=acc0, acc3=acc0;
        for (int k=0;k<DD;k+=4){
            float4 t0 = ld4(sT + (r0+0)*PITCH + k);
            float4 t1 = ld4(sT + (r0+1)*PITCH + k);
            float4 t2 = ld4(sT + (r0+2)*PITCH + k);
            float4 t3 = ld4(sT + (r0+3)*PITCH + k);
            float4 f0 = ld4(sFt + (k+0)*PITCH + c0);
            acc0=fma4(t0.x,f0,acc0); acc1=fma4(t1.x,f0,acc1); acc2=fma4(t2.x,f0,acc2); acc3=fma4(t3.x,f0,acc3);
            float4 f1 = ld4(sFt + (k+1)*PITCH + c0);
            acc0=fma4(t0.y,f1,acc0); acc1=fma4(t1.y,f1,acc1); acc2=fma4(t2.y,f1,acc2); acc3=fma4(t3.y,f1,acc3);
            float4 f2 = ld4(sFt + (k+2)*PITCH + c0);
            acc0=fma4(t0.z,f2,acc0); acc1=fma4(t1.z,f2,acc1); acc2=fma4(t2.z,f2,acc2); acc3=fma4(t3.z,f2,acc3);
            float4 f3 = ld4(sFt + (k+3)*PITCH + c0);
            acc0=fma4(t0.w,f3,acc0); acc1=fma4(t1.w,f3,acc1); acc2=fma4(t2.w,f3,acc2); acc3=fma4(t3.w,f3,acc3);
        }
        // Q = pnf pnf^T + diag(exp(pnd))
        float pa[4][3], pb[4][3];
        #pragma unroll
        for (int i=0;i<4;i++)
            #pragma unroll
            for (int r=0;r<3;r++){
                pa[i][r] = g_pnf[(r0+i)*3 + r];
                pb[i][r] = g_pnf[(c0+i)*3 + r];
            }
        float* accp[4] = { &acc0.x, &acc1.x, &acc2.x, &acc3.x };
        #pragma unroll
        for (int i=0;i<4;i++){
            #pragma unroll
            for (int j=0;j<4;j++){
                float q = pa[i][0]*pb[j][0];
                q = fmaf(pa[i][1], pb[j][1], q);
                q = fmaf(pa[i][2], pb[j][2], q);
                accp[i][j] += q;
            }
        }
        if (r0 == c0){
            #pragma unroll
            for (int i=0;i<4;i++) accp[i][i] += expf(g_pnd[r0+i]);
        }
        st4(sP + (r0+0)*PITCH + c0, acc0);
        st4(sP + (r0+1)*PITCH + c0, acc1);
        st4(sP + (r0+2)*PITCH + c0, acc2);
        st4(sP + (r0+3)*PITCH + c0, acc3);
    }
    __syncthreads();

    // ---------------- HP = Hw @ pred_cov  [32][64] ----------------
    {
        const int o0 = ty*2, c0 = tx*4;
        float4 accA = make_float4(0,0,0,0), accB = accA;
        for (int k=0;k<DD;k+=4){
            float4 h0 = ld4(sHw + (o0+0)*PITCH + k);
            float4 h1 = ld4(sHw + (o0+1)*PITCH + k);
            float4 p0 = ld4(sP + (k+0)*PITCH + c0);
            accA=fma4(h0.x,p0,accA); accB=fma4(h1.x,p0,accB);
            float4 p1 = ld4(sP + (k+1)*PITCH + c0);
            accA=fma4(h0.y,p1,accA); accB=fma4(h1.y,p1,accB);
            float4 p2 = ld4(sP + (k+2)*PITCH + c0);
            accA=fma4(h0.z,p2,accA); accB=fma4(h1.z,p2,accB);
            float4 p3 = ld4(sP + (k+3)*PITCH + c0);
            accA=fma4(h0.w,p3,accA); accB=fma4(h1.w,p3,accB);
        }
        st4(sHP + (o0+0)*PITCH + c0, accA);
        st4(sHP + (o0+1)*PITCH + c0, accB);
    }
    __syncthreads();

    // ---------------- S = HP @ Hw^T + Rn  [32][32] ----------------
    {
        const int o0 = ty*2, p0 = tx*2;
        float a00=0.f,a01=0.f,a10=0.f,a11=0.f;
        for (int k=0;k<DD;k+=4){
            float4 x0 = ld4(sHP + (o0+0)*PITCH + k);
            float4 x1 = ld4(sHP + (o0+1)*PITCH + k);
            float4 y0 = ld4(sHw + (p0+0)*PITCH + k);
            float4 y1 = ld4(sHw + (p0+1)*PITCH + k);
            a00 = dot4acc(x0,y0,a00); a01 = dot4acc(x0,y1,a01);
            a10 = dot4acc(x1,y0,a10); a11 = dot4acc(x1,y1,a11);
        }
        float oa[2][3], ob[2][3];
        #pragma unroll
        for (int i=0;i<2;i++)
            #pragma unroll
            for (int r=0;r<3;r++){
                oa[i][r] = g_onf[(o0+i)*3 + r];
                ob[i][r] = g_onf[(p0+i)*3 + r];
            }
        a00 += oa[0][0]*ob[0][0] + oa[0][1]*ob[0][1] + oa[0][2]*ob[0][2];
        a01 += oa[0][0]*ob[1][0] + oa[0][1]*ob[1][1] + oa[0][2]*ob[1][2];
        a10 += oa[1][0]*ob[0][0] + oa[1][1]*ob[0][1] + oa[1][2]*ob[0][2];
        a11 += oa[1][0]*ob[1][0] + oa[1][1]*ob[1][1] + oa[1][2]*ob[1][2];
        if (o0 == p0){
            a00 += expf(g_ond[o0+0]);
            a11 += expf(g_ond[o0+1]);
        }
        sS[(o0+0)*SPITCH + p0+0] = a00;
        sS[(o0+0)*SPITCH + p0+1] = a01;
        sS[(o0+1)*SPITCH + p0+0] = a10;
        sS[(o0+1)*SPITCH + p0+1] = a11;
    }
    __syncthreads();

    // ---------------- Cholesky (in place) + log_det + L^{-1} : warp 0 ----------------
    if (tid < 32) {
        const int i = tid;
        for (int j=0;j<32;j++){
            float s = 0.f;
            if (i >= j){
                s = sS[i*SPITCH + j];
                for (int k=0;k<j;k++) s = fmaf(-sS[i*SPITCH+k], sS[j*SPITCH+k], s);
            }
            float dj  = __shfl_sync(0xffffffffu, s, j);
            float ljj = sqrtf(dj);
            if (i == j)      sS[i*SPITCH+j] = ljj;
            else if (i > j)  sS[i*SPITCH+j] = s / ljj;
            __syncwarp();
        }
        float ld = logf(sS[i*SPITCH+i]);
        #pragma unroll
        for (int off=16;off;off>>=1) ld += __shfl_xor_sync(0xffffffffu, ld, off);
        if (i == 0) sred[0] = 2.f*ld;
        // forward substitution: column i of L^{-1}
        for (int r=0;r<32;r++){
            float rhs = (r == i) ? 1.f : 0.f;
            for (int k=0;k<r;k++) rhs = fmaf(-sS[r*SPITCH+k], sLi[k*SPITCH+i], rhs);
            sLi[r*SPITCH+i] = (r >= i) ? rhs / sS[r*SPITCH+r] : 0.f;
            __syncwarp();
        }
    }
    __syncthreads();

    // ---------------- S_inv = Linv^T @ Linv ----------------
    {
        const int o0 = ty*2, p0 = tx*2;
        float a00=0.f,a01=0.f,a10=0.f,a11=0.f;
        #pragma unroll 8
        for (int k=0;k<32;k++){
            float x0 = sLi[k*SPITCH + o0], x1 = sLi[k*SPITCH + o0+1];
            float y0 = sLi[k*SPITCH + p0], y1 = sLi[k*SPITCH + p0+1];
            a00 = fmaf(x0,y0,a00); a01 = fmaf(x0,y1,a01);
            a10 = fmaf(x1,y0,a10); a11 = fmaf(x1,y1,a11);
        }
        sSi[(o0+0)*SPITCH + p0+0] = a00;
        sSi[(o0+0)*SPITCH + p0+1] = a01;
        sSi[(o0+1)*SPITCH + p0+0] = a10;
        sSi[(o0+1)*SPITCH + p0+1] = a11;
    }
    __syncthreads();

    // ---------------- Kg = HP^T @ S_inv  [64][32] ----------------
    {
        const int r0 = ty*4, p0 = tx*2;
        float acc[4][2] = {};
        #pragma unroll 4
        for (int o=0;o<32;o++){
            float4 a = ld4(sHP + o*PITCH + r0);
            float s0 = sSi[o*SPITCH + p0], s1 = sSi[o*SPITCH + p0+1];
            acc[0][0]=fmaf(a.x,s0,acc[0][0]); acc[0][1]=fmaf(a.x,s1,acc[0][1]);
            acc[1][0]=fmaf(a.y,s0,acc[1][0]); acc[1][1]=fmaf(a.y,s1,acc[1][1]);
            acc[2][0]=fmaf(a.z,s0,acc[2][0]); acc[2][1]=fmaf(a.z,s1,acc[2][1]);
            acc[3][0]=fmaf(a.w,s0,acc[3][0]); acc[3][1]=fmaf(a.w,s1,acc[3][1]);
        }
        #pragma unroll
        for (int i=0;i<4;i++){
            sKg[(r0+i)*SPITCH + p0  ] = acc[i][0];
            sKg[(r0+i)*SPITCH + p0+1] = acc[i][1];
        }
    }
    __syncthreads();

    // ---------------- post_mean, log_likelihood ----------------
    if (tid < DD) {
        float acc = spm[tid];
        #pragma unroll 8
        for (int o=0;o<OO;o++) acc = fmaf(sKg[tid*SPITCH+o], sinn[o], acc);
        o_mean[(size_t)b*DD + tid] = acc;
    }
    if (tid >= 64 && tid < 96) {   // warp 2: quad form + ll
        int o = tid - 64;
        float t = 0.f;
        #pragma unroll 8
        for (int p=0;p<OO;p++) t = fmaf(sSi[o*SPITCH+p], sinn[p], t);
        float q = t * sinn[o];
        #pragma unroll
        for (int off=16;off;off>>=1) q += __shfl_xor_sync(0xffffffffu, q, off);
        if (o == 0) o_ll[b] = -0.5f*(sred[0] + q + 32.f*LOG2PI);
    }

    // ---------------- post_cov = pred_cov - Kg @ HP ----------------
    {
        const int r0 = ty*4, c0 = tx*4;
        float4 acc0=make_float4(0,0,0,0), acc1=acc0, acc2=acc0, acc3=acc0;
        for (int o=0;o<32;o+=4){
            float4 k0 = ld4(sKg + (r0+0)*SPITCH + o);
            float4 k1 = ld4(sKg + (r0+1)*SPITCH + o);
            float4 k2 = ld4(sKg + (r0+2)*SPITCH + o);
            float4 k3 = ld4(sKg + (r0+3)*SPITCH + o);
            float4 h0 = ld4(sHP + (o+0)*PITCH + c0);
            acc0=fma4(k0.x,h0,acc0); acc1=fma4(k1.x,h0,acc1); acc2=fma4(k2.x,h0,acc2); acc3=fma4(k3.x,h0,acc3);
            float4 h1 = ld4(sHP + (o+1)*PITCH + c0);
            acc0=fma4(k0.y,h1,acc0); acc1=fma4(k1.y,h1,acc1); acc2=fma4(k2.y,h1,acc2); acc3=fma4(k3.y,h1,acc3);
            float4 h2 = ld4(sHP + (o+2)*PITCH + c0);
            acc0=fma4(k0.z,h2,acc0); acc1=fma4(k1.z,h2,acc1); acc2=fma4(k2.z,h2,acc2); acc3=fma4(k3.z,h2,acc3);
            float4 h3 = ld4(sHP + (o+3)*PITCH + c0);
            acc0=fma4(k0.w,h3,acc0); acc1=fma4(k1.w,h3,acc1); acc2=fma4(k2.w,h3,acc2); acc3=fma4(k3.w,h3,acc3);
        }
        float* outr = o_cov + (size_t)b*4096;
        float4 accs[4] = {acc0, acc1, acc2, acc3};
        #pragma unroll
        for (int i=0;i<4;i++){
            float4 pc = ld4(sP + (r0+i)*PITCH + c0);
            float4 res = make_float4(pc.x - accs[i].x, pc.y - accs[i].y,
                                     pc.z - accs[i].z, pc.w - accs[i].w);
            st4(outr + (r0+i)*64 + c0, res);
        }
    }
}

extern "C" void kernel_launch(void* const* d_in, const int* in_sizes, int n_in,
                              void* d_out, int out_size)
{
    const float* g_mean  = (const float*)d_in[0];
    const float* g_cov   = (const float*)d_in[1];
    const float* g_obs   = (const float*)d_in[2];
    const float* g_w1    = (const float*)d_in[3];
    const float* g_b1    = (const float*)d_in[4];
    const float* g_w2    = (const float*)d_in[5];
    const float* g_b2    = (const float*)d_in[6];
    const float* g_basis = (const float*)d_in[7];
    const float* g_pnf   = (const float*)d_in[8];
    const float* g_pnd   = (const float*)d_in[9];
    const float* g_onf   = (const float*)d_in[10];
    const float* g_ond   = (const float*)d_in[11];
    const float* g_Hw    = (const float*)d_in[12];
    const float* g_Hb    = (const float*)d_in[13];

    const int B = in_sizes[0] / DD;
    float* out    = (float*)d_out;
    float* o_mean = out;
    float* o_cov  = out + (size_t)B*DD;
    float* o_ll   = out + (size_t)B*DD + (size_t)B*DD*DD;

    const int smem_bytes = SMEM_FLOATS * (int)sizeof(float);
    cudaFuncSetAttribute(rkn_kernel, cudaFuncAttributeMaxDynamicSharedMemorySize, smem_bytes);
    rkn_kernel<<<B, BDIM, smem_bytes>>>(g_mean, g_cov, g_obs, g_w1, g_b1, g_w2, g_b2,
                                        g_basis, g_pnf, g_pnd, g_onf, g_ond, g_Hw, g_Hb,
                                        o_mean, o_cov, o_ll);
}